// round 2
// baseline (speedup 1.0000x reference)
#include <cuda_runtime.h>
#include <math.h>

// ---------------- problem constants ----------------
#define HW       4096
#define CCH      256
#define S_ELEMS  16777216LL              // 4096*4096
#define NM_ELEMS 2097152LL               // 2*4096*256
#define ZONE_THR 411.041792f             // (0.028^2 * 512^2 * 2)
#define NMS_THR  8.388608f               // (0.004^2 * 512^2 * 2)

// ---------------- device scratch (static = allowed) ----------------
static __device__ float g_sim   [2ULL*16777216ULL]; // sim[n][i][j]
static __device__ float g_sim12 [16777216ULL];      // mean over n
static __device__ float g_sim12T[16777216ULL];      // transpose
static __device__ float g_xn[2097152];              // normalized x1, (n,i,c)
static __device__ float g_rn[2097152];              // normalized x2, (n,c,i)
static __device__ float g_den1[8192];
static __device__ float g_den2[8192];
static __device__ int   g_mid_idx[4096];
static __device__ int   g_max_idx[4096];
static __device__ float g_asim[4096];
static __device__ float g_msim[4096];
static __device__ int   g_mask12[4096];
static __device__ int   g_mask21[4096];
static __device__ int   g_indexA[4096];  // rows with mask12
static __device__ int   g_indexB[4096];  // rows with mask21
static __device__ int   g_sigA[4096];    // 'indices' values (12-side)
static __device__ int   g_mfA[4096];
static __device__ int   g_sigB[4096];
static __device__ int   g_mfB[4096];
static __device__ long long g_base;      // dynamic base offset for big outputs

// pdist2 element, replicating XLA-CPU bit-exactly:
//   sum(a*a,-1): unfused mul+add  -> rnd(rnd(ax^2)+rnd(ay^2))
//   matmul (Eigen gebp, K=2):     -> fma(ay,by, rnd(ax*bx))
//   d = |rnd(sa+sb) - 2*dt|
// The self point gives d==0 only when sa == dt bitwise — matching the
// reference's (d_temp == 0) NMS keep-term row for row.
__device__ __forceinline__ float pd2(float ax, float ay, float bx, float by) {
    float sa = __fadd_rn(__fmul_rn(ax, ax), __fmul_rn(ay, ay));
    float sb = __fadd_rn(__fmul_rn(bx, bx), __fmul_rn(by, by));
    float dt = __fmaf_rn(ay, by, __fmul_rn(ax, bx));
    return fabsf(__fsub_rn(__fadd_rn(sa, sb), __fmul_rn(2.0f, dt)));
}

// ---------------- norms per spatial position ----------------
__global__ void norms_kernel(const float* __restrict__ x1, const float* __restrict__ x2) {
    int lane = threadIdx.x & 31, w = threadIdx.x >> 5;
    int n = blockIdx.y;
    int i = blockIdx.x * 32 + lane;
    const float* p1 = x1 + (size_t)n * (CCH * HW) + i;
    const float* p2 = x2 + (size_t)n * (CCH * HW) + i;
    float s1 = 0.f, s2 = 0.f;
    for (int c = w; c < CCH; c += 8) {
        float a = p1[(size_t)c << 12]; s1 += a * a;
        float b = p2[(size_t)c << 12]; s2 += b * b;
    }
    __shared__ float sh1[8][32], sh2[8][32];
    sh1[w][lane] = s1; sh2[w][lane] = s2;
    __syncthreads();
    if (w == 0) {
        float a = 0.f, b = 0.f;
        #pragma unroll
        for (int q = 0; q < 8; q++) { a += sh1[q][lane]; b += sh2[q][lane]; }
        g_den1[n * HW + i] = fmaxf(sqrtf(a), 1e-12f);
        g_den2[n * HW + i] = fmaxf(sqrtf(b), 1e-12f);
    }
}

// normalized x2 in (n,c,i) layout (same as input)
__global__ void norm_ref_kernel(const float* __restrict__ x2) {
    size_t stride = (size_t)gridDim.x * blockDim.x;
    for (size_t t = (size_t)blockIdx.x * blockDim.x + threadIdx.x; t < (size_t)NM_ELEMS; t += stride) {
        int n = (int)(t >> 20);
        int i = (int)(t & 4095);
        g_rn[t] = x2[t] / g_den2[(n << 12) | i];
    }
}

// normalized x1 transposed to (n,i,c)
__global__ void xpose_norm_kernel(const float* __restrict__ x1) {
    __shared__ float tile[32][33];
    int n = blockIdx.z, c0 = blockIdx.y * 32, i0 = blockIdx.x * 32;
    int tx = threadIdx.x, ty = threadIdx.y;
    for (int r = ty; r < 32; r += 8)
        tile[r][tx] = x1[(size_t)(n * CCH + c0 + r) * HW + i0 + tx];
    __syncthreads();
    for (int r = ty; r < 32; r += 8) {
        int i = i0 + r;
        g_xn[((size_t)(n * HW + i)) * CCH + c0 + tx] = tile[tx][r] / g_den1[n * HW + i];
    }
}

// ---------------- fp32 SIMT GEMM: sim[n] = Xn(4096x256) * Rn(256x4096) ----------------
__global__ void __launch_bounds__(256, 2) sgemm_kernel() {
    const float* A = g_xn + (size_t)blockIdx.z * HW * CCH;       // (M,K) row-major
    const float* B = g_rn + (size_t)blockIdx.z * CCH * HW;       // (K,N) row-major
    float*       Co = g_sim + (size_t)blockIdx.z * S_ELEMS;
    __shared__ float As[16][128];
    __shared__ float Bs[16][128];
    int tid = threadIdx.x;
    int m0 = blockIdx.y * 128, n0 = blockIdx.x * 128;
    int tr = tid >> 4, tc = tid & 15;
    float acc[8][8];
    #pragma unroll
    for (int a = 0; a < 8; a++)
        #pragma unroll
        for (int b = 0; b < 8; b++) acc[a][b] = 0.f;
    float ar[8], br[8];
    for (int k0 = 0; k0 < CCH; k0 += 16) {
        #pragma unroll
        for (int s = 0; s < 8; s++) {
            int l = tid + s * 256; int m = l >> 4, k = l & 15;
            As[k][m] = A[(size_t)(m0 + m) * CCH + k0 + k];
        }
        #pragma unroll
        for (int s = 0; s < 8; s++) {
            int l = tid + s * 256; int k = l >> 7, c = l & 127;
            Bs[k][c] = B[(size_t)(k0 + k) * HW + n0 + c];
        }
        __syncthreads();
        #pragma unroll
        for (int k = 0; k < 16; k++) {
            #pragma unroll
            for (int u = 0; u < 8; u++) ar[u] = As[k][tr * 8 + u];
            #pragma unroll
            for (int u = 0; u < 8; u++) br[u] = Bs[k][tc * 8 + u];
            #pragma unroll
            for (int a = 0; a < 8; a++)
                #pragma unroll
                for (int b = 0; b < 8; b++) acc[a][b] = fmaf(ar[a], br[b], acc[a][b]);
        }
        __syncthreads();
    }
    #pragma unroll
    for (int a = 0; a < 8; a++)
        #pragma unroll
        for (int b = 0; b < 8; b++)
            Co[(size_t)(m0 + tr * 8 + a) * HW + n0 + tc * 8 + b] = acc[a][b];
}

// ---------------- mean over batch + transpose ----------------
__global__ void avg_tr_kernel() {
    __shared__ float tile[32][33];
    int i0 = blockIdx.y * 32, j0 = blockIdx.x * 32;
    int tx = threadIdx.x, ty = threadIdx.y;
    for (int r = ty; r < 32; r += 8) {
        size_t idx = (size_t)(i0 + r) * HW + j0 + tx;
        float v = (g_sim[idx] + g_sim[S_ELEMS + idx]) * 0.5f;
        g_sim12[idx] = v;
        tile[r][tx] = v;
    }
    __syncthreads();
    for (int r = ty; r < 32; r += 8)
        g_sim12T[(size_t)(j0 + r) * HW + i0 + tx] = tile[tx][r];
}

// ---------------- association (one block per row) ----------------
__global__ void assoc_kernel(const float* __restrict__ fkpVar, const float* __restrict__ fkpFix, int dir) {
    __shared__ float px[4096], py[4096];
    __shared__ float sv[256]; __shared__ int si[256];
    __shared__ float r0[256], r1[256];
    const float* simM = dir ? g_sim12T : g_sim12;
    int*   oI = dir ? g_max_idx : g_mid_idx;
    float* oS = dir ? g_msim    : g_asim;
    int*   oM = dir ? g_mask21  : g_mask12;

    int i = blockIdx.x, tid = threadIdx.x;
    for (int j = tid; j < HW; j += 256) { px[j] = fkpVar[2 * j]; py[j] = fkpVar[2 * j + 1]; }
    float qx = fkpFix[2 * i], qy = fkpFix[2 * i + 1];
    __syncthreads();
    const float* row = simM + (size_t)i * HW;

    // pass 1: argmax of v = sim*mz, tie -> smallest index
    float bv = -INFINITY; int bi = 0x7fffffff;
    for (int j = tid; j < HW; j += 256) {
        float s = row[j];
        float d = pd2(qx, qy, px[j], py[j]);
        float v = s * ((d < ZONE_THR) ? 1.0f : 0.0f);
        if (v > bv || (v == bv && j < bi)) { bv = v; bi = j; }
    }
    sv[tid] = bv; si[tid] = bi;
    __syncthreads();
    for (int o = 128; o > 0; o >>= 1) {
        if (tid < o) {
            float v2 = sv[tid + o]; int i2 = si[tid + o];
            if (v2 > sv[tid] || (v2 == sv[tid] && i2 < si[tid])) { sv[tid] = v2; si[tid] = i2; }
        }
        __syncthreads();
    }
    int idx0 = si[0];
    float rx = px[idx0], ry = py[idx0];

    // pass 2: top-2 values of v * nms
    float t0 = -INFINITY, t1 = -INFINITY;
    for (int j = tid; j < HW; j += 256) {
        float s = row[j];
        float d = pd2(qx, qy, px[j], py[j]);
        float v = s * ((d < ZONE_THR) ? 1.0f : 0.0f);
        float dt = pd2(rx, ry, px[j], py[j]);
        float v2 = v * ((dt >= NMS_THR || dt == 0.0f) ? 1.0f : 0.0f);
        if (v2 > t0) { t1 = t0; t0 = v2; } else if (v2 > t1) { t1 = v2; }
    }
    r0[tid] = t0; r1[tid] = t1;
    __syncthreads();
    for (int o = 128; o > 0; o >>= 1) {
        if (tid < o) {
            float a0 = r0[tid], a1 = r1[tid], b0 = r0[tid + o], b1 = r1[tid + o];
            r0[tid] = fmaxf(a0, b0);
            r1[tid] = fmaxf(fminf(a0, b0), fmaxf(a1, b1));
        }
        __syncthreads();
    }
    if (tid == 0) {
        float v0 = r0[0], v1 = r1[0];
        oI[i] = idx0;
        oS[i] = v0;
        oM[i] = (v1 < v0 * 0.995f && v0 > 0.75f) ? 1 : 0;
    }
}

// ---------------- block scan helper (1024 threads) ----------------
__device__ __forceinline__ int scan1024(int loc, int tid, int* s_warp, int* total) {
    int lane = tid & 31, w = tid >> 5;
    int v = loc;
    #pragma unroll
    for (int o = 1; o < 32; o <<= 1) { int u = __shfl_up_sync(0xffffffffu, v, o); if (lane >= o) v += u; }
    if (lane == 31) s_warp[w] = v;
    __syncthreads();
    if (w == 0) {
        int x = s_warp[lane];
        #pragma unroll
        for (int o = 1; o < 32; o <<= 1) { int u = __shfl_up_sync(0xffffffffu, x, o); if (lane >= o) x += u; }
        s_warp[lane] = x;
    }
    __syncthreads();
    int pre = v - loc + (w ? s_warp[w - 1] : 0);
    *total = s_warp[31];
    __syncthreads();
    return pre;
}

// ---------------- finalize: counts, compaction, small outputs ----------------
__global__ void finalize_kernel(float* __restrict__ out) {
    __shared__ int s_warp[32];
    __shared__ int sh_k12, sh_k21, sh_cm, sh_cm2;
    int tid = threadIdx.x;
    int tot;

    // phase 1: mask12 -> g_indexA, k12
    {
        int f[4], loc = 0;
        #pragma unroll
        for (int r = 0; r < 4; r++) { f[r] = g_mask12[tid * 4 + r]; loc += f[r]; }
        int pre = scan1024(loc, tid, s_warp, &tot);
        int p = pre;
        #pragma unroll
        for (int r = 0; r < 4; r++) if (f[r]) g_indexA[p++] = tid * 4 + r;
        if (tid == 0) sh_k12 = tot;
    }
    __syncthreads();
    // phase 2: mask21 -> g_indexB, k21
    {
        int f[4], loc = 0;
        #pragma unroll
        for (int r = 0; r < 4; r++) { f[r] = g_mask21[tid * 4 + r]; loc += f[r]; }
        int pre = scan1024(loc, tid, s_warp, &tot);
        int p = pre;
        #pragma unroll
        for (int r = 0; r < 4; r++) if (f[r]) g_indexB[p++] = tid * 4 + r;
        if (tid == 0) sh_k21 = tot;
    }
    __syncthreads();
    int k12 = sh_k12, k21 = sh_k21;

    // phase 3: signed gathers + mutual flags
    #pragma unroll
    for (int r = 0; r < 4; r++) {
        int u = tid * 4 + r;
        if (u < k12) {
            int rw = g_indexA[u];
            int mid = g_mid_idx[rw];
            int s21 = g_mask21[mid] ? g_max_idx[mid] : (-g_max_idx[mid] - 2);
            g_sigA[u] = s21;
            g_mfA[u] = (rw == s21) ? 1 : 0;
        } else g_mfA[u] = 0;
        if (u < k21) {
            int rw = g_indexB[u];
            int mx = g_max_idx[rw];
            int s12 = g_mask12[mx] ? g_mid_idx[mx] : (-g_mid_idx[mx] - 2);
            g_sigB[u] = s12;
            g_mfB[u] = (rw == s12) ? 1 : 0;
        } else g_mfB[u] = 0;
    }
    __syncthreads();

    // phase 4: compact index_valid (12) straight into out
    {
        int f[4], loc = 0;
        #pragma unroll
        for (int r = 0; r < 4; r++) { f[r] = g_mfA[tid * 4 + r]; loc += f[r]; }
        int pre = scan1024(loc, tid, s_warp, &tot);
        int p = pre;
        long long o3 = (long long)k12 + 8192;
        #pragma unroll
        for (int r = 0; r < 4; r++) if (f[r]) out[o3 + (p++)] = (float)g_indexA[tid * 4 + r];
        if (tid == 0) sh_cm = tot;
    }
    __syncthreads();
    int cm = sh_cm;
    // phase 5: compact index_valid2 (21)
    {
        int f[4], loc = 0;
        #pragma unroll
        for (int r = 0; r < 4; r++) { f[r] = g_mfB[tid * 4 + r]; loc += f[r]; }
        int pre = scan1024(loc, tid, s_warp, &tot);
        int p = pre;
        long long o4 = (long long)k12 + 8192 + cm;
        #pragma unroll
        for (int r = 0; r < 4; r++) if (f[r]) out[o4 + (p++)] = (float)g_indexB[tid * 4 + r];
        if (tid == 0) sh_cm2 = tot;
    }
    __syncthreads();
    int cm2 = sh_cm2;

    // phase 6: remaining small outputs + base offset
    for (int u = tid; u < k12; u += 1024) out[u] = (float)g_sigA[u];
    #pragma unroll
    for (int r = 0; r < 4; r++) {
        int u = tid * 4 + r;
        out[(long long)k12 + u]        = (float)g_max_idx[u];
        out[(long long)k12 + 4096 + u] = (float)g_mid_idx[u];
    }
    long long base = (long long)k12 + 8192 + cm + cm2;
    long long o11 = base + 4 * S_ELEMS + 2 * NM_ELEMS;
    #pragma unroll
    for (int r = 0; r < 4; r++) {
        int u = tid * 4 + r;
        out[o11 + u]        = g_mask12[u] ? 1.0f : 0.0f;
        out[o11 + 4096 + u] = g_asim[u];
        out[o11 + 8192 + u] = g_msim[u];
    }
    if (tid == 0) g_base = base;
}

// ---------------- big writers ----------------
__global__ void write_simpair_kernel(float* __restrict__ out) {
    long long b = g_base;
    size_t stride = (size_t)gridDim.x * blockDim.x;
    for (size_t t = (size_t)blockIdx.x * blockDim.x + threadIdx.x; t < (size_t)S_ELEMS; t += stride) {
        out[b + t] = g_sim12[t];
        out[b + S_ELEMS + t] = g_sim12T[t];
    }
}
__global__ void write_dzone_kernel(float* __restrict__ out,
                                   const float* __restrict__ fkp1, const float* __restrict__ fkp2) {
    long long b = g_base;
    long long o7 = b + 2 * S_ELEMS;
    long long o10 = b + 3 * S_ELEMS + 2 * NM_ELEMS;
    size_t stride = (size_t)gridDim.x * blockDim.x;
    for (size_t t = (size_t)blockIdx.x * blockDim.x + threadIdx.x; t < (size_t)S_ELEMS; t += stride) {
        int i = (int)(t >> 12), j = (int)(t & 4095);
        float d = pd2(fkp1[2 * i], fkp1[2 * i + 1], fkp2[2 * j], fkp2[2 * j + 1]);
        out[o7 + t] = (d < ZONE_THR) ? 1.0f : 0.0f;
        out[o10 + t] = d;
    }
}
__global__ void write_norm_kernel(float* __restrict__ out) {
    long long b = g_base;
    long long o8 = b + 3 * S_ELEMS;
    long long o9 = o8 + NM_ELEMS;
    size_t stride = (size_t)gridDim.x * blockDim.x;
    for (size_t t = (size_t)blockIdx.x * blockDim.x + threadIdx.x; t < (size_t)NM_ELEMS; t += stride) {
        out[o8 + t] = g_xn[t];
        out[o9 + t] = g_rn[t];
    }
}
__global__ void write_simbig_kernel(float* __restrict__ out) {
    long long o14 = g_base + 4 * S_ELEMS + 2 * NM_ELEMS + 12288;
    size_t stride = (size_t)gridDim.x * blockDim.x;
    for (size_t t = (size_t)blockIdx.x * blockDim.x + threadIdx.x; t < (size_t)(2 * S_ELEMS); t += stride) {
        out[o14 + t] = g_sim[t];
    }
}

// ---------------- launcher ----------------
extern "C" void kernel_launch(void* const* d_in, const int* in_sizes, int n_in,
                              void* d_out, int out_size) {
    const float* x1   = (const float*)d_in[0];
    const float* x2   = (const float*)d_in[1];
    const float* fkp1 = (const float*)d_in[2];
    const float* fkp2 = (const float*)d_in[3];
    float* out = (float*)d_out;
    (void)in_sizes; (void)n_in; (void)out_size;

    norms_kernel<<<dim3(128, 2), 256>>>(x1, x2);
    norm_ref_kernel<<<2048, 256>>>(x2);
    xpose_norm_kernel<<<dim3(128, 8, 2), dim3(32, 8)>>>(x1);
    sgemm_kernel<<<dim3(32, 32, 2), 256>>>();
    avg_tr_kernel<<<dim3(128, 128), dim3(32, 8)>>>();
    assoc_kernel<<<4096, 256>>>(fkp2, fkp1, 0);
    assoc_kernel<<<4096, 256>>>(fkp1, fkp2, 1);
    finalize_kernel<<<1, 1024>>>(out);
    write_simpair_kernel<<<4096, 256>>>(out);
    write_dzone_kernel<<<4096, 256>>>(out, fkp1, fkp2);
    write_norm_kernel<<<2048, 256>>>(out);
    write_simbig_kernel<<<8192, 256>>>(out);
}

// round 3
// speedup vs baseline: 1.6777x; 1.6777x over previous
#include <cuda_runtime.h>
#include <math.h>
#include <stdint.h>

// ---------------- problem constants ----------------
#define HW       4096
#define CCH      256
#define S_ELEMS  16777216LL              // 4096*4096
#define NM_ELEMS 2097152LL               // 2*4096*256
#define ZONE_THR 411.041792f             // (0.028^2 * 512^2 * 2)
#define NMS_THR  8.388608f               // (0.004^2 * 512^2 * 2)

// ---------------- device scratch (static = allowed) ----------------
static __device__ float g_sim   [2ULL*16777216ULL]; // sim[n][i][j]
static __device__ float g_sim12 [16777216ULL];      // mean over n
static __device__ float g_sim12T[16777216ULL];      // transpose
static __device__ float g_xn[2097152];              // normalized x1, (n,i,c)
static __device__ float g_rn[2097152];              // normalized x2, (n,c,i)
static __device__ float g_den1[8192];
static __device__ float g_den2[8192];
static __device__ int   g_mid_idx[4096];
static __device__ int   g_max_idx[4096];
static __device__ float g_asim[4096];
static __device__ float g_msim[4096];
static __device__ int   g_mask12[4096];
static __device__ int   g_mask21[4096];
static __device__ int   g_indexA[4096];
static __device__ int   g_indexB[4096];
static __device__ int   g_sigA[4096];
static __device__ int   g_mfA[4096];
static __device__ int   g_sigB[4096];
static __device__ int   g_mfB[4096];
static __device__ long long g_base;

// pdist2, replicating XLA-CPU bit-exactly (unfused squares, FMA dot)
__device__ __forceinline__ float pd2(float ax, float ay, float bx, float by) {
    float sa = __fadd_rn(__fmul_rn(ax, ax), __fmul_rn(ay, ay));
    float sb = __fadd_rn(__fmul_rn(bx, bx), __fmul_rn(by, by));
    float dt = __fmaf_rn(ay, by, __fmul_rn(ax, bx));
    return fabsf(__fsub_rn(__fadd_rn(sa, sb), __fmul_rn(2.0f, dt)));
}

// ---------------- norms per spatial position ----------------
__global__ void norms_kernel(const float* __restrict__ x1, const float* __restrict__ x2) {
    int lane = threadIdx.x & 31, w = threadIdx.x >> 5;
    int n = blockIdx.y;
    int i = blockIdx.x * 32 + lane;
    const float* p1 = x1 + (size_t)n * (CCH * HW) + i;
    const float* p2 = x2 + (size_t)n * (CCH * HW) + i;
    float s1 = 0.f, s2 = 0.f;
    for (int c = w; c < CCH; c += 8) {
        float a = p1[(size_t)c << 12]; s1 += a * a;
        float b = p2[(size_t)c << 12]; s2 += b * b;
    }
    __shared__ float sh1[8][32], sh2[8][32];
    sh1[w][lane] = s1; sh2[w][lane] = s2;
    __syncthreads();
    if (w == 0) {
        float a = 0.f, b = 0.f;
        #pragma unroll
        for (int q = 0; q < 8; q++) { a += sh1[q][lane]; b += sh2[q][lane]; }
        g_den1[n * HW + i] = fmaxf(sqrtf(a), 1e-12f);
        g_den2[n * HW + i] = fmaxf(sqrtf(b), 1e-12f);
    }
}

// normalized x2 in (n,c,i) layout
__global__ void norm_ref_kernel(const float* __restrict__ x2) {
    size_t stride = (size_t)gridDim.x * blockDim.x;
    for (size_t t = (size_t)blockIdx.x * blockDim.x + threadIdx.x; t < (size_t)NM_ELEMS; t += stride) {
        int n = (int)(t >> 20);
        int i = (int)(t & 4095);
        g_rn[t] = x2[t] / g_den2[(n << 12) | i];
    }
}

// normalized x1 transposed to (n,i,c)
__global__ void xpose_norm_kernel(const float* __restrict__ x1) {
    __shared__ float tile[32][33];
    int n = blockIdx.z, c0 = blockIdx.y * 32, i0 = blockIdx.x * 32;
    int tx = threadIdx.x, ty = threadIdx.y;
    for (int r = ty; r < 32; r += 8)
        tile[r][tx] = x1[(size_t)(n * CCH + c0 + r) * HW + i0 + tx];
    __syncthreads();
    for (int r = ty; r < 32; r += 8) {
        int i = i0 + r;
        g_xn[((size_t)(n * HW + i)) * CCH + c0 + tx] = tile[tx][r] / g_den1[n * HW + i];
    }
}

// ---------------- tf32 tensor-core GEMM ----------------
__device__ __forceinline__ uint32_t f2tf32(float f) {
    uint32_t u; asm("cvt.rna.tf32.f32 %0, %1;" : "=r"(u) : "f"(f)); return u;
}
__device__ __forceinline__ void mma_tf32(float* c, const uint32_t* a, const uint32_t* b) {
    asm volatile("mma.sync.aligned.m16n8k8.row.col.f32.tf32.tf32.f32 "
        "{%0,%1,%2,%3}, {%4,%5,%6,%7}, {%8,%9}, {%0,%1,%2,%3};"
        : "+f"(c[0]), "+f"(c[1]), "+f"(c[2]), "+f"(c[3])
        : "r"(a[0]), "r"(a[1]), "r"(a[2]), "r"(a[3]), "r"(b[0]), "r"(b[1]));
}

// C[4096x4096] = A[4096x256] * B[256x4096] per batch.
// Block tile 128x128, 8 warps of 32x64, k-chunk 32.
// A stored in shared in mma-fragment-permuted layout (one LDS.128 per frag).
__global__ void __launch_bounds__(256) mma_gemm_kernel() {
    __shared__ uint32_t As[4096];        // [mt(8)][ks(4)][lane(32)][slot(4)]
    __shared__ uint32_t Bs[32][136];     // [k][n], pad 8 -> conflict-free frags
    const float* A  = g_xn + (size_t)blockIdx.z * (HW * (size_t)CCH);
    const float* B  = g_rn + (size_t)blockIdx.z * ((size_t)CCH * HW);
    float*       Co = g_sim + (size_t)blockIdx.z * S_ELEMS;
    int m0 = blockIdx.y * 128, n0 = blockIdx.x * 128;
    int tid = threadIdx.x, lane = tid & 31, w = tid >> 5;
    int wm = w & 3, wn = w >> 2;         // warp tile: rows 32*wm, cols 64*wn

    float acc[2][8][4];
    #pragma unroll
    for (int mi = 0; mi < 2; mi++)
        #pragma unroll
        for (int nt = 0; nt < 8; nt++)
            #pragma unroll
            for (int r = 0; r < 4; r++) acc[mi][nt][r] = 0.f;

    for (int kc = 0; kc < CCH; kc += 32) {
        // ---- fill A (fragment-permuted) ----
        #pragma unroll
        for (int q = 0; q < 4; q++) {
            int m  = 32 * q + (tid >> 3);
            int kb = 4 * (tid & 7);
            float4 v = *(const float4*)&A[(size_t)(m0 + m) * CCH + kc + kb];
            int mt = m >> 4, lm = m & 15;
            float vv[4] = {v.x, v.y, v.z, v.w};
            #pragma unroll
            for (int j = 0; j < 4; j++) {
                int k = kb + j, ks = k >> 3, kk = k & 7;
                int ln   = (lm & 7) * 4 + (kk & 3);
                int slot = (lm >> 3) + ((kk >> 2) << 1);
                As[((mt * 4 + ks) * 32 + ln) * 4 + slot] = f2tf32(vv[j]);
            }
        }
        // ---- fill B ----
        #pragma unroll
        for (int q = 0; q < 4; q++) {
            int k = 8 * q + (tid >> 5);
            int c = 4 * (tid & 31);
            float4 v = *(const float4*)&B[(size_t)(kc + k) * HW + n0 + c];
            uint4 u;
            u.x = f2tf32(v.x); u.y = f2tf32(v.y); u.z = f2tf32(v.z); u.w = f2tf32(v.w);
            *(uint4*)&Bs[k][c] = u;
        }
        __syncthreads();
        // ---- compute ----
        #pragma unroll
        for (int ks = 0; ks < 4; ks++) {
            uint32_t af[2][4];
            #pragma unroll
            for (int mi = 0; mi < 2; mi++) {
                uint4 t4 = *(const uint4*)&As[(((2 * wm + mi) * 4 + ks) * 32 + lane) * 4];
                af[mi][0] = t4.x; af[mi][1] = t4.y; af[mi][2] = t4.z; af[mi][3] = t4.w;
            }
            #pragma unroll
            for (int nt = 0; nt < 8; nt++) {
                uint32_t bf[2];
                int n = 64 * wn + 8 * nt + (lane >> 2);
                bf[0] = Bs[ks * 8 + (lane & 3)][n];
                bf[1] = Bs[ks * 8 + (lane & 3) + 4][n];
                mma_tf32(acc[0][nt], af[0], bf);
                mma_tf32(acc[1][nt], af[1], bf);
            }
        }
        __syncthreads();
    }
    // ---- epilogue ----
    #pragma unroll
    for (int mi = 0; mi < 2; mi++) {
        int row0 = m0 + 32 * wm + 16 * mi + (lane >> 2);
        #pragma unroll
        for (int nt = 0; nt < 8; nt++) {
            int col = n0 + 64 * wn + 8 * nt + 2 * (lane & 3);
            *(float2*)&Co[(size_t)row0 * HW + col]       = make_float2(acc[mi][nt][0], acc[mi][nt][1]);
            *(float2*)&Co[(size_t)(row0 + 8) * HW + col] = make_float2(acc[mi][nt][2], acc[mi][nt][3]);
        }
    }
}

// ---------------- mean over batch + transpose ----------------
__global__ void avg_tr_kernel() {
    __shared__ float tile[32][33];
    int i0 = blockIdx.y * 32, j0 = blockIdx.x * 32;
    int tx = threadIdx.x, ty = threadIdx.y;
    for (int r = ty; r < 32; r += 8) {
        size_t idx = (size_t)(i0 + r) * HW + j0 + tx;
        float v = (g_sim[idx] + g_sim[S_ELEMS + idx]) * 0.5f;
        g_sim12[idx] = v;
        tile[r][tx] = v;
    }
    __syncthreads();
    for (int r = ty; r < 32; r += 8)
        g_sim12T[(size_t)(j0 + r) * HW + i0 + tx] = tile[tx][r];
}

// ---------------- association (one block per row) ----------------
__global__ void assoc_kernel(const float* __restrict__ fkpVar, const float* __restrict__ fkpFix, int dir) {
    __shared__ float px[4096], py[4096];
    __shared__ float sv[256]; __shared__ int si[256];
    __shared__ float r0[256], r1[256];
    const float* simM = dir ? g_sim12T : g_sim12;
    int*   oI = dir ? g_max_idx : g_mid_idx;
    float* oS = dir ? g_msim    : g_asim;
    int*   oM = dir ? g_mask21  : g_mask12;

    int i = blockIdx.x, tid = threadIdx.x;
    for (int j = tid; j < HW; j += 256) { px[j] = fkpVar[2 * j]; py[j] = fkpVar[2 * j + 1]; }
    float qx = fkpFix[2 * i], qy = fkpFix[2 * i + 1];
    __syncthreads();
    const float* row = simM + (size_t)i * HW;

    float bv = -INFINITY; int bi = 0x7fffffff;
    for (int j = tid; j < HW; j += 256) {
        float s = row[j];
        float d = pd2(qx, qy, px[j], py[j]);
        float v = s * ((d < ZONE_THR) ? 1.0f : 0.0f);
        if (v > bv || (v == bv && j < bi)) { bv = v; bi = j; }
    }
    sv[tid] = bv; si[tid] = bi;
    __syncthreads();
    for (int o = 128; o > 0; o >>= 1) {
        if (tid < o) {
            float v2 = sv[tid + o]; int i2 = si[tid + o];
            if (v2 > sv[tid] || (v2 == sv[tid] && i2 < si[tid])) { sv[tid] = v2; si[tid] = i2; }
        }
        __syncthreads();
    }
    int idx0 = si[0];
    float rx = px[idx0], ry = py[idx0];

    float t0 = -INFINITY, t1 = -INFINITY;
    for (int j = tid; j < HW; j += 256) {
        float s = row[j];
        float d = pd2(qx, qy, px[j], py[j]);
        float v = s * ((d < ZONE_THR) ? 1.0f : 0.0f);
        float dt = pd2(rx, ry, px[j], py[j]);
        float v2 = v * ((dt >= NMS_THR || dt == 0.0f) ? 1.0f : 0.0f);
        if (v2 > t0) { t1 = t0; t0 = v2; } else if (v2 > t1) { t1 = v2; }
    }
    r0[tid] = t0; r1[tid] = t1;
    __syncthreads();
    for (int o = 128; o > 0; o >>= 1) {
        if (tid < o) {
            float a0 = r0[tid], a1 = r1[tid], b0 = r0[tid + o], b1 = r1[tid + o];
            r0[tid] = fmaxf(a0, b0);
            r1[tid] = fmaxf(fminf(a0, b0), fmaxf(a1, b1));
        }
        __syncthreads();
    }
    if (tid == 0) {
        float v0 = r0[0], v1 = r1[0];
        oI[i] = idx0;
        oS[i] = v0;
        oM[i] = (v1 < v0 * 0.995f && v0 > 0.75f) ? 1 : 0;
    }
}

// ---------------- block scan helper (1024 threads) ----------------
__device__ __forceinline__ int scan1024(int loc, int tid, int* s_warp, int* total) {
    int lane = tid & 31, w = tid >> 5;
    int v = loc;
    #pragma unroll
    for (int o = 1; o < 32; o <<= 1) { int u = __shfl_up_sync(0xffffffffu, v, o); if (lane >= o) v += u; }
    if (lane == 31) s_warp[w] = v;
    __syncthreads();
    if (w == 0) {
        int x = s_warp[lane];
        #pragma unroll
        for (int o = 1; o < 32; o <<= 1) { int u = __shfl_up_sync(0xffffffffu, x, o); if (lane >= o) x += u; }
        s_warp[lane] = x;
    }
    __syncthreads();
    int pre = v - loc + (w ? s_warp[w - 1] : 0);
    *total = s_warp[31];
    __syncthreads();
    return pre;
}

// ---------------- finalize ----------------
__global__ void finalize_kernel(float* __restrict__ out) {
    __shared__ int s_warp[32];
    __shared__ int sh_k12, sh_k21, sh_cm, sh_cm2;
    int tid = threadIdx.x;
    int tot;

    {
        int f[4], loc = 0;
        #pragma unroll
        for (int r = 0; r < 4; r++) { f[r] = g_mask12[tid * 4 + r]; loc += f[r]; }
        int pre = scan1024(loc, tid, s_warp, &tot);
        int p = pre;
        #pragma unroll
        for (int r = 0; r < 4; r++) if (f[r]) g_indexA[p++] = tid * 4 + r;
        if (tid == 0) sh_k12 = tot;
    }
    __syncthreads();
    {
        int f[4], loc = 0;
        #pragma unroll
        for (int r = 0; r < 4; r++) { f[r] = g_mask21[tid * 4 + r]; loc += f[r]; }
        int pre = scan1024(loc, tid, s_warp, &tot);
        int p = pre;
        #pragma unroll
        for (int r = 0; r < 4; r++) if (f[r]) g_indexB[p++] = tid * 4 + r;
        if (tid == 0) sh_k21 = tot;
    }
    __syncthreads();
    int k12 = sh_k12, k21 = sh_k21;

    #pragma unroll
    for (int r = 0; r < 4; r++) {
        int u = tid * 4 + r;
        if (u < k12) {
            int rw = g_indexA[u];
            int mid = g_mid_idx[rw];
            int s21 = g_mask21[mid] ? g_max_idx[mid] : (-g_max_idx[mid] - 2);
            g_sigA[u] = s21;
            g_mfA[u] = (rw == s21) ? 1 : 0;
        } else g_mfA[u] = 0;
        if (u < k21) {
            int rw = g_indexB[u];
            int mx = g_max_idx[rw];
            int s12 = g_mask12[mx] ? g_mid_idx[mx] : (-g_mid_idx[mx] - 2);
            g_sigB[u] = s12;
            g_mfB[u] = (rw == s12) ? 1 : 0;
        } else g_mfB[u] = 0;
    }
    __syncthreads();

    {
        int f[4], loc = 0;
        #pragma unroll
        for (int r = 0; r < 4; r++) { f[r] = g_mfA[tid * 4 + r]; loc += f[r]; }
        int pre = scan1024(loc, tid, s_warp, &tot);
        int p = pre;
        long long o3 = (long long)k12 + 8192;
        #pragma unroll
        for (int r = 0; r < 4; r++) if (f[r]) out[o3 + (p++)] = (float)g_indexA[tid * 4 + r];
        if (tid == 0) sh_cm = tot;
    }
    __syncthreads();
    int cm = sh_cm;
    {
        int f[4], loc = 0;
        #pragma unroll
        for (int r = 0; r < 4; r++) { f[r] = g_mfB[tid * 4 + r]; loc += f[r]; }
        int pre = scan1024(loc, tid, s_warp, &tot);
        int p = pre;
        long long o4 = (long long)k12 + 8192 + cm;
        #pragma unroll
        for (int r = 0; r < 4; r++) if (f[r]) out[o4 + (p++)] = (float)g_indexB[tid * 4 + r];
        if (tid == 0) sh_cm2 = tot;
    }
    __syncthreads();
    int cm2 = sh_cm2;

    for (int u = tid; u < k12; u += 1024) out[u] = (float)g_sigA[u];
    #pragma unroll
    for (int r = 0; r < 4; r++) {
        int u = tid * 4 + r;
        out[(long long)k12 + u]        = (float)g_max_idx[u];
        out[(long long)k12 + 4096 + u] = (float)g_mid_idx[u];
    }
    long long base = (long long)k12 + 8192 + cm + cm2;
    long long o11 = base + 4 * S_ELEMS + 2 * NM_ELEMS;
    #pragma unroll
    for (int r = 0; r < 4; r++) {
        int u = tid * 4 + r;
        out[o11 + u]        = g_mask12[u] ? 1.0f : 0.0f;
        out[o11 + 4096 + u] = g_asim[u];
        out[o11 + 8192 + u] = g_msim[u];
    }
    if (tid == 0) g_base = base;
}

// ---------------- big writers ----------------
__global__ void write_simpair_kernel(float* __restrict__ out) {
    long long b = g_base;
    size_t stride = (size_t)gridDim.x * blockDim.x;
    for (size_t t = (size_t)blockIdx.x * blockDim.x + threadIdx.x; t < (size_t)S_ELEMS; t += stride) {
        out[b + t] = g_sim12[t];
        out[b + S_ELEMS + t] = g_sim12T[t];
    }
}
__global__ void write_dzone_kernel(float* __restrict__ out,
                                   const float* __restrict__ fkp1, const float* __restrict__ fkp2) {
    long long b = g_base;
    long long o7 = b + 2 * S_ELEMS;
    long long o10 = b + 3 * S_ELEMS + 2 * NM_ELEMS;
    size_t stride = (size_t)gridDim.x * blockDim.x;
    for (size_t t = (size_t)blockIdx.x * blockDim.x + threadIdx.x; t < (size_t)S_ELEMS; t += stride) {
        int i = (int)(t >> 12), j = (int)(t & 4095);
        float d = pd2(fkp1[2 * i], fkp1[2 * i + 1], fkp2[2 * j], fkp2[2 * j + 1]);
        out[o7 + t] = (d < ZONE_THR) ? 1.0f : 0.0f;
        out[o10 + t] = d;
    }
}
__global__ void write_norm_kernel(float* __restrict__ out) {
    long long b = g_base;
    long long o8 = b + 3 * S_ELEMS;
    long long o9 = o8 + NM_ELEMS;
    size_t stride = (size_t)gridDim.x * blockDim.x;
    for (size_t t = (size_t)blockIdx.x * blockDim.x + threadIdx.x; t < (size_t)NM_ELEMS; t += stride) {
        out[o8 + t] = g_xn[t];
        out[o9 + t] = g_rn[t];
    }
}
__global__ void write_simbig_kernel(float* __restrict__ out) {
    long long o14 = g_base + 4 * S_ELEMS + 2 * NM_ELEMS + 12288;
    size_t stride = (size_t)gridDim.x * blockDim.x;
    for (size_t t = (size_t)blockIdx.x * blockDim.x + threadIdx.x; t < (size_t)(2 * S_ELEMS); t += stride) {
        out[o14 + t] = g_sim[t];
    }
}

// ---------------- launcher ----------------
extern "C" void kernel_launch(void* const* d_in, const int* in_sizes, int n_in,
                              void* d_out, int out_size) {
    const float* x1   = (const float*)d_in[0];
    const float* x2   = (const float*)d_in[1];
    const float* fkp1 = (const float*)d_in[2];
    const float* fkp2 = (const float*)d_in[3];
    float* out = (float*)d_out;
    (void)in_sizes; (void)n_in; (void)out_size;

    norms_kernel<<<dim3(128, 2), 256>>>(x1, x2);
    norm_ref_kernel<<<2048, 256>>>(x2);
    xpose_norm_kernel<<<dim3(128, 8, 2), dim3(32, 8)>>>(x1);
    mma_gemm_kernel<<<dim3(32, 32, 2), 256>>>();
    avg_tr_kernel<<<dim3(128, 128), dim3(32, 8)>>>();
    assoc_kernel<<<4096, 256>>>(fkp2, fkp1, 0);
    assoc_kernel<<<4096, 256>>>(fkp1, fkp2, 1);
    finalize_kernel<<<1, 1024>>>(out);
    write_simpair_kernel<<<4096, 256>>>(out);
    write_dzone_kernel<<<4096, 256>>>(out, fkp1, fkp2);
    write_norm_kernel<<<2048, 256>>>(out);
    write_simbig_kernel<<<8192, 256>>>(out);
}